// round 13
// baseline (speedup 1.0000x reference)
#include <cuda_runtime.h>
#include <cstdint>

// ---------------- problem constants ----------------
#define NUM_USERS   100000
#define NUM_ITEMS   50000
#define DUMMYIDX    150000
#define BATCH       4096
#define NPOSW       16384
#define NNEGW       32768
#define WLEN        11
#define NWIN        7
#define CTXW        5
#define POS_ROWS    (NPOSW * NWIN)
#define NEG_ROWS    (NNEGW * NWIN)
#define POS_ELEMS   (POS_ROWS * CTXW)   // 573440
#define NEG_ELEMS   (NEG_ROWS * CTXW)   // 1146880
#define POS_LOGITS  (POS_ROWS * 4)
#define NEG_LOGITS  (NEG_ROWS * 4)

// ---------------- scratch ----------------
__device__ int   g_pos[NPOSW * WLEN];
__device__ int   g_neg[NNEGW * WLEN];
__device__ float g_acc[2];

struct Keys10  { uint32_t k[10][2]; };
struct KeysR10 { uint32_t kh[10][2]; uint32_t kl[10][2]; };  // randint's internal split keys

// ---------------- threefry-2x32, 20 rounds ----------------
__host__ __device__ __forceinline__ void tf2x32(uint32_t k0, uint32_t k1,
                                                uint32_t x0, uint32_t x1,
                                                uint32_t& o0, uint32_t& o1) {
    uint32_t ks2 = k0 ^ k1 ^ 0x1BD11BDAu;
    x0 += k0; x1 += k1;
#define TFR(r) { x0 += x1; x1 = (x1 << (r)) | (x1 >> (32 - (r))); x1 ^= x0; }
    TFR(13) TFR(15) TFR(26) TFR(6)
    x0 += k1;  x1 += ks2 + 1u;
    TFR(17) TFR(29) TFR(16) TFR(24)
    x0 += ks2; x1 += k0 + 2u;
    TFR(13) TFR(15) TFR(26) TFR(6)
    x0 += k0;  x1 += k1 + 3u;
    TFR(17) TFR(29) TFR(16) TFR(24)
    x0 += k1;  x1 += ks2 + 4u;
    TFR(13) TFR(15) TFR(26) TFR(6)
    x0 += ks2; x1 += k0 + 5u;
#undef TFR
    o0 = x0; o1 = x1;
}

// modern partitionable 32-bit bits: xor of lanes at counter (0, i)  [VERIFIED via pos]
__device__ __forceinline__ uint32_t rbits_modern(uint32_t k0, uint32_t k1, uint32_t i) {
    uint32_t a, b;
    tf2x32(k0, k1, 0u, i, a, b);
    return a ^ b;
}

// ---------------- kernels ----------------
__global__ void zero_kernel() {
    if (threadIdx.x == 0) { g_acc[0] = 0.0f; g_acc[1] = 0.0f; }
}

__global__ void __launch_bounds__(256) pos_walk_kernel(
    Keys10 keys, const int* __restrict__ batch,
    const int* __restrict__ rowptr_ui, const int* __restrict__ col_ui,
    const int* __restrict__ rowcount_ui, int nnz_ui,
    const int* __restrict__ rowptr_iu, const int* __restrict__ col_iu,
    const int* __restrict__ rowcount_iu, int nnz_iu)
{
    int t = blockIdx.x * blockDim.x + threadIdx.x;
    if (t >= NPOSW) return;
    int cur = batch[t & (BATCH - 1)];
    g_pos[t * WLEN + 0] = cur + NUM_ITEMS;   // START_USER

    #pragma unroll
    for (int i = 0; i < 10; i++) {
        uint32_t bits = rbits_modern(keys.k[i][0], keys.k[i][1], (uint32_t)t);
        float r = __uint_as_float((bits >> 9) | 0x3f800000u) - 1.0f;

        const int *rowptr, *col, *rowcount;
        int nnz, nrows;
        if ((i & 1) == 0) { rowptr = rowptr_ui; col = col_ui; rowcount = rowcount_ui; nnz = nnz_ui; nrows = NUM_USERS; }
        else              { rowptr = rowptr_iu; col = col_iu; rowcount = rowcount_iu; nnz = nnz_iu; nrows = NUM_ITEMS; }

        bool mask = (cur >= DUMMYIDX);
        int s = cur; if (s < 0) s = 0; if (s > nrows - 1) s = nrows - 1;
        int count = rowcount[s];
        int idx = (int)(r * (float)count) + rowptr[s];
        if (idx > nnz - 1) idx = nnz - 1;
        int nxt = col[idx];
        if (mask || count == 0) nxt = DUMMYIDX;
        cur = nxt;

        int off = ((i + 1) & 1) ? 0 : NUM_ITEMS;
        int adj = cur + off;
        if (adj > DUMMYIDX) adj = DUMMYIDX;
        g_pos[t * WLEN + i + 1] = adj;
    }
}

// neg: SPLIT-KEY randint hypothesis — randint internally does
//   k_hi, k_lo = split(sk); higher = bits(k_hi, shape); lower = bits(k_lo, shape)
//   (keys precomputed host-side), combine with wrapped u32 multiplier:
//   users span 1e5: m=0 -> ro = lo % span;  items span 5e4: m=17296
__global__ void __launch_bounds__(256) neg_walk_kernel(KeysR10 keys, const int* __restrict__ batch)
{
    int t = blockIdx.x * blockDim.x + threadIdx.x;
    if (t >= NNEGW) return;
    int cur = batch[t & (BATCH - 1)];
    g_neg[t * WLEN + 0] = cur + NUM_ITEMS;

    #pragma unroll
    for (int i = 0; i < 10; i++) {
        uint32_t span = ((i & 1) == 0) ? (uint32_t)NUM_ITEMS : (uint32_t)NUM_USERS;
        uint32_t hi = rbits_modern(keys.kh[i][0], keys.kh[i][1], (uint32_t)t);
        uint32_t lo = rbits_modern(keys.kl[i][0], keys.kl[i][1], (uint32_t)t);
        uint32_t m = 65536u % span;
        m = (m * m) % span;                       // u32 wraparound (0 for span=1e5)
        uint32_t ro = ((hi % span) * m + (lo % span)) % span;
        cur = (int)ro;
        int off = ((i + 1) & 1) ? 0 : NUM_ITEMS;
        g_neg[t * WLEN + i + 1] = cur + off;
    }
}

__global__ void __launch_bounds__(256) emit_kernel(float* __restrict__ out)
{
    int e = blockIdx.x * blockDim.x + threadIdx.x;
    if (e >= POS_ELEMS + NEG_ELEMS) return;
    int val;
    if (e < POS_ELEMS) {
        int w = e / CTXW, c = e % CTXW;
        int j = w / NPOSW, t = w % NPOSW;
        val = g_pos[t * WLEN + j + c];
    } else {
        int e2 = e - POS_ELEMS;
        int w = e2 / CTXW, c = e2 % CTXW;
        int j = w / NNEGW, t = w % NNEGW;
        val = g_neg[t * WLEN + j + c];
    }
    out[1 + e] = (float)val;
}

// one warp per walk: 11 emb rows in registers, 28 window dots, log-sigmoid terms
__global__ void __launch_bounds__(256) loss_kernel(const float* __restrict__ emb)
{
    int warp = (blockIdx.x * blockDim.x + threadIdx.x) >> 5;
    int lane = threadIdx.x & 31;
    bool is_pos;
    const int* walks;
    int w;
    if (warp < NPOSW) { is_pos = true;  walks = g_pos; w = warp; }
    else              { is_pos = false; walks = g_neg; w = warp - NPOSW; }

    int myn = (lane < WLEN) ? walks[w * WLEN + lane] : 0;

    float4 v[WLEN];
    #pragma unroll
    for (int j = 0; j < WLEN; j++) {
        int nj = __shfl_sync(0xffffffffu, myn, j);
        v[j] = *reinterpret_cast<const float4*>(emb + (size_t)nj * 128 + lane * 4);
    }

    float lsum = 0.0f;
    #pragma unroll
    for (int j = 0; j < NWIN; j++) {
        #pragma unroll
        for (int c = 1; c <= 4; c++) {
            float4 a = v[j], b = v[j + c];
            float p = a.x * b.x + a.y * b.y + a.z * b.z + a.w * b.w;
            #pragma unroll
            for (int o = 16; o > 0; o >>= 1) p += __shfl_xor_sync(0xffffffffu, p, o);
            float s = 1.0f / (1.0f + expf(-p));
            lsum += is_pos ? -logf(s + 1e-15f) : -logf(1.0f - s + 1e-15f);
        }
    }

    __shared__ float sh[8];
    if (lane == 0) sh[threadIdx.x >> 5] = lsum;
    __syncthreads();
    if (threadIdx.x == 0) {
        float bs = 0.0f;
        #pragma unroll
        for (int i = 0; i < 8; i++) bs += sh[i];
        atomicAdd(&g_acc[is_pos ? 0 : 1], bs);
    }
}

__global__ void finalize_kernel(float* __restrict__ out)
{
    if (threadIdx.x == 0)
        out[0] = g_acc[0] * (1.0f / (float)POS_LOGITS) + g_acc[1] * (1.0f / (float)NEG_LOGITS);
}

// ---------------- launch ----------------
// foldlike split [VERIFIED]: new key = H(key; 0,0), subkey = H(key; 0,1)
static void foldlike_split(uint32_t k0, uint32_t k1,
                           uint32_t& nk0, uint32_t& nk1,
                           uint32_t& sk0, uint32_t& sk1)
{
    tf2x32(k0, k1, 0u, 0u, nk0, nk1);
    tf2x32(k0, k1, 0u, 1u, sk0, sk1);
}

extern "C" void kernel_launch(void* const* d_in, const int* in_sizes, int n_in,
                              void* d_out, int out_size)
{
    const float* emb        = (const float*)d_in[0];
    const int* rowptr_ui    = (const int*)d_in[1];
    const int* col_ui       = (const int*)d_in[2];
    const int* rowcount_ui  = (const int*)d_in[3];
    const int* rowptr_iu    = (const int*)d_in[4];
    const int* col_iu       = (const int*)d_in[5];
    const int* rowcount_iu  = (const int*)d_in[6];
    const int* batch        = (const int*)d_in[7];
    int nnz_ui = in_sizes[2];
    int nnz_iu = in_sizes[5];
    float* out = (float*)d_out;

    uint32_t kp0, kp1, kn0, kn1;
    foldlike_split(0u, 42u, kp0, kp1, kn0, kn1);

    Keys10 pk;
    KeysR10 nkr;
    uint32_t c0 = kp0, c1 = kp1;
    for (int i = 0; i < 10; i++) {
        uint32_t n0, n1, s0, s1;
        foldlike_split(c0, c1, n0, n1, s0, s1);
        pk.k[i][0] = s0; pk.k[i][1] = s1;
        c0 = n0; c1 = n1;
    }
    c0 = kn0; c1 = kn1;
    for (int i = 0; i < 10; i++) {
        uint32_t n0, n1, s0, s1;
        foldlike_split(c0, c1, n0, n1, s0, s1);   // chain key + step subkey sk_i
        // randint internal: k_hi, k_lo = split(sk_i)
        uint32_t h0, h1, l0, l1;
        foldlike_split(s0, s1, h0, h1, l0, l1);
        nkr.kh[i][0] = h0; nkr.kh[i][1] = h1;
        nkr.kl[i][0] = l0; nkr.kl[i][1] = l1;
        c0 = n0; c1 = n1;
    }

    zero_kernel<<<1, 32>>>();
    pos_walk_kernel<<<NPOSW / 256, 256>>>(pk, batch,
        rowptr_ui, col_ui, rowcount_ui, nnz_ui, rowptr_iu, col_iu, rowcount_iu, nnz_iu);
    neg_walk_kernel<<<NNEGW / 256, 256>>>(nkr, batch);
    emit_kernel<<<(POS_ELEMS + NEG_ELEMS + 255) / 256, 256>>>(out);
    loss_kernel<<<(NPOSW + NNEGW) / 8, 256>>>(emb);
    finalize_kernel<<<1, 32>>>(out);
}

// round 14
// speedup vs baseline: 1.8458x; 1.8458x over previous
#include <cuda_runtime.h>
#include <cstdint>

// ---------------- problem constants ----------------
#define NUM_USERS   100000
#define NUM_ITEMS   50000
#define DUMMYIDX    150000
#define BATCH       4096
#define NPOSW       16384
#define NNEGW       32768
#define WLEN        11
#define NWIN        7
#define CTXW        5
#define POS_ROWS    (NPOSW * NWIN)
#define NEG_ROWS    (NNEGW * NWIN)
#define POS_ELEMS   (POS_ROWS * CTXW)   // 573440
#define NEG_ELEMS   (NEG_ROWS * CTXW)   // 1146880
#define POS_LOGITS  (POS_ROWS * 4)
#define NEG_LOGITS  (NEG_ROWS * 4)

// ---------------- scratch ----------------
__device__ int   g_pos[NPOSW * WLEN];
__device__ int   g_neg[NNEGW * WLEN];
__device__ float g_acc[2];

struct Keys10  { uint32_t k[10][2]; };
struct KeysR10 { uint32_t kh[10][2]; uint32_t kl[10][2]; };

// ---------------- threefry-2x32, 20 rounds [VERIFIED] ----------------
__host__ __device__ __forceinline__ void tf2x32(uint32_t k0, uint32_t k1,
                                                uint32_t x0, uint32_t x1,
                                                uint32_t& o0, uint32_t& o1) {
    uint32_t ks2 = k0 ^ k1 ^ 0x1BD11BDAu;
    x0 += k0; x1 += k1;
#define TFR(r) { x0 += x1; x1 = (x1 << (r)) | (x1 >> (32 - (r))); x1 ^= x0; }
    TFR(13) TFR(15) TFR(26) TFR(6)
    x0 += k1;  x1 += ks2 + 1u;
    TFR(17) TFR(29) TFR(16) TFR(24)
    x0 += ks2; x1 += k0 + 2u;
    TFR(13) TFR(15) TFR(26) TFR(6)
    x0 += k0;  x1 += k1 + 3u;
    TFR(17) TFR(29) TFR(16) TFR(24)
    x0 += k1;  x1 += ks2 + 4u;
    TFR(13) TFR(15) TFR(26) TFR(6)
    x0 += ks2; x1 += k0 + 5u;
#undef TFR
    o0 = x0; o1 = x1;
}

__device__ __forceinline__ uint32_t rbits_modern(uint32_t k0, uint32_t k1, uint32_t i) {
    uint32_t a, b;
    tf2x32(k0, k1, 0u, i, a, b);
    return a ^ b;
}

// ---------------- kernels ----------------
__global__ void __launch_bounds__(256) pos_walk_kernel(
    Keys10 keys, const int* __restrict__ batch,
    const int* __restrict__ rowptr_ui, const int* __restrict__ col_ui,
    const int* __restrict__ rowcount_ui, int nnz_ui,
    const int* __restrict__ rowptr_iu, const int* __restrict__ col_iu,
    const int* __restrict__ rowcount_iu, int nnz_iu)
{
    int t = blockIdx.x * blockDim.x + threadIdx.x;
    if (t == 0) { g_acc[0] = 0.0f; g_acc[1] = 0.0f; }   // loss runs after us on same stream
    if (t >= NPOSW) return;
    int cur = batch[t & (BATCH - 1)];
    g_pos[t * WLEN + 0] = cur + NUM_ITEMS;

    #pragma unroll
    for (int i = 0; i < 10; i++) {
        uint32_t bits = rbits_modern(keys.k[i][0], keys.k[i][1], (uint32_t)t);
        float r = __uint_as_float((bits >> 9) | 0x3f800000u) - 1.0f;

        const int *rowptr, *col, *rowcount;
        int nnz, nrows;
        if ((i & 1) == 0) { rowptr = rowptr_ui; col = col_ui; rowcount = rowcount_ui; nnz = nnz_ui; nrows = NUM_USERS; }
        else              { rowptr = rowptr_iu; col = col_iu; rowcount = rowcount_iu; nnz = nnz_iu; nrows = NUM_ITEMS; }

        bool mask = (cur >= DUMMYIDX);
        int s = cur; if (s < 0) s = 0; if (s > nrows - 1) s = nrows - 1;
        int count = rowcount[s];
        int idx = (int)(r * (float)count) + rowptr[s];
        if (idx > nnz - 1) idx = nnz - 1;
        int nxt = col[idx];
        if (mask || count == 0) nxt = DUMMYIDX;
        cur = nxt;

        int off = ((i + 1) & 1) ? 0 : NUM_ITEMS;
        int adj = cur + off;
        if (adj > DUMMYIDX) adj = DUMMYIDX;
        g_pos[t * WLEN + i + 1] = adj;
    }
}

// neg: split-key randint [VERIFIED]
__global__ void __launch_bounds__(256) neg_walk_kernel(KeysR10 keys, const int* __restrict__ batch)
{
    int t = blockIdx.x * blockDim.x + threadIdx.x;
    if (t >= NNEGW) return;
    int cur = batch[t & (BATCH - 1)];
    g_neg[t * WLEN + 0] = cur + NUM_ITEMS;

    #pragma unroll
    for (int i = 0; i < 10; i++) {
        uint32_t span = ((i & 1) == 0) ? (uint32_t)NUM_ITEMS : (uint32_t)NUM_USERS;
        uint32_t hi = rbits_modern(keys.kh[i][0], keys.kh[i][1], (uint32_t)t);
        uint32_t lo = rbits_modern(keys.kl[i][0], keys.kl[i][1], (uint32_t)t);
        uint32_t m = 65536u % span;
        m = (m * m) % span;
        uint32_t ro = ((hi % span) * m + (lo % span)) % span;
        cur = (int)ro;
        int off = ((i + 1) & 1) ? 0 : NUM_ITEMS;
        g_neg[t * WLEN + i + 1] = cur + off;
    }
}

__global__ void __launch_bounds__(256) emit_kernel(float* __restrict__ out)
{
    int e = blockIdx.x * blockDim.x + threadIdx.x;
    if (e >= POS_ELEMS + NEG_ELEMS) return;
    int val;
    if (e < POS_ELEMS) {
        int w = e / CTXW, c = e % CTXW;
        int j = w / NPOSW, t = w % NPOSW;
        val = g_pos[t * WLEN + j + c];
    } else {
        int e2 = e - POS_ELEMS;
        int w = e2 / CTXW, c = e2 % CTXW;
        int j = w / NNEGW, t = w % NNEGW;
        val = g_neg[t * WLEN + j + c];
    }
    out[1 + e] = (float)val;
}

// packed f32x2 dot helper: returns lo+hi of fma2(ahi,bhi, mul2(alo,blo))
__device__ __forceinline__ float dot128_partial(unsigned long long alo, unsigned long long ahi,
                                                unsigned long long blo, unsigned long long bhi)
{
    unsigned long long acc;
    asm("mul.rn.f32x2 %0, %1, %2;" : "=l"(acc) : "l"(alo), "l"(blo));
    asm("fma.rn.f32x2 %0, %1, %2, %3;" : "=l"(acc) : "l"(ahi), "l"(bhi), "l"(acc));
    uint32_t lo, hi;
    asm("mov.b64 {%0,%1}, %2;" : "=r"(lo), "=r"(hi) : "l"(acc));
    return __uint_as_float(lo) + __uint_as_float(hi);
}

// one warp per walk; transcendental chain lane-distributed (1 chain per warp, not 28)
__global__ void __launch_bounds__(256) loss_kernel(const float* __restrict__ emb)
{
    int warp = (blockIdx.x * blockDim.x + threadIdx.x) >> 5;
    int lane = threadIdx.x & 31;
    bool is_pos;
    const int* walks;
    int w;
    if (warp < NPOSW) { is_pos = true;  walks = g_pos; w = warp; }
    else              { is_pos = false; walks = g_neg; w = warp - NPOSW; }

    int myn = (lane < WLEN) ? walks[w * WLEN + lane] : 0;

    unsigned long long vlo[WLEN], vhi[WLEN];
    #pragma unroll
    for (int j = 0; j < WLEN; j++) {
        int nj = __shfl_sync(0xffffffffu, myn, j);
        ulonglong2 q = *reinterpret_cast<const ulonglong2*>(emb + (size_t)nj * 128 + lane * 4);
        vlo[j] = q.x; vhi[j] = q.y;
    }

    float myp = 0.0f;
    #pragma unroll
    for (int j = 0; j < NWIN; j++) {
        #pragma unroll
        for (int c = 1; c <= 4; c++) {
            float p = dot128_partial(vlo[j], vhi[j], vlo[j + c], vhi[j + c]);
            #pragma unroll
            for (int o = 16; o > 0; o >>= 1) p += __shfl_xor_sync(0xffffffffu, p, o);
            int k = j * 4 + (c - 1);
            if (lane == k) myp = p;       // park logit k on lane k
        }
    }

    // one sigmoid/log chain per warp, 28 active lanes (EXACT same per-term formula as before)
    float s = __fdividef(1.0f, 1.0f + __expf(-myp));
    float x = is_pos ? s : (1.0f - s);
    float term = -__logf(x + 1e-15f);
    if (lane >= 28) term = 0.0f;
    #pragma unroll
    for (int o = 16; o > 0; o >>= 1) term += __shfl_xor_sync(0xffffffffu, term, o);

    __shared__ float sh[8];
    if (lane == 0) sh[threadIdx.x >> 5] = term;
    __syncthreads();
    if (threadIdx.x == 0) {
        float bs = 0.0f;
        #pragma unroll
        for (int i = 0; i < 8; i++) bs += sh[i];
        atomicAdd(&g_acc[is_pos ? 0 : 1], bs);   // block uniformly pos or neg (16384 % 8 == 0)
    }
}

__global__ void finalize_kernel(float* __restrict__ out)
{
    if (threadIdx.x == 0)
        out[0] = g_acc[0] * (1.0f / (float)POS_LOGITS) + g_acc[1] * (1.0f / (float)NEG_LOGITS);
}

// ---------------- launch ----------------
static void foldlike_split(uint32_t k0, uint32_t k1,
                           uint32_t& nk0, uint32_t& nk1,
                           uint32_t& sk0, uint32_t& sk1)
{
    tf2x32(k0, k1, 0u, 0u, nk0, nk1);
    tf2x32(k0, k1, 0u, 1u, sk0, sk1);
}

extern "C" void kernel_launch(void* const* d_in, const int* in_sizes, int n_in,
                              void* d_out, int out_size)
{
    const float* emb        = (const float*)d_in[0];
    const int* rowptr_ui    = (const int*)d_in[1];
    const int* col_ui       = (const int*)d_in[2];
    const int* rowcount_ui  = (const int*)d_in[3];
    const int* rowptr_iu    = (const int*)d_in[4];
    const int* col_iu       = (const int*)d_in[5];
    const int* rowcount_iu  = (const int*)d_in[6];
    const int* batch        = (const int*)d_in[7];
    int nnz_ui = in_sizes[2];
    int nnz_iu = in_sizes[5];
    float* out = (float*)d_out;

    uint32_t kp0, kp1, kn0, kn1;
    foldlike_split(0u, 42u, kp0, kp1, kn0, kn1);

    Keys10 pk;
    KeysR10 nkr;
    uint32_t c0 = kp0, c1 = kp1;
    for (int i = 0; i < 10; i++) {
        uint32_t n0, n1, s0, s1;
        foldlike_split(c0, c1, n0, n1, s0, s1);
        pk.k[i][0] = s0; pk.k[i][1] = s1;
        c0 = n0; c1 = n1;
    }
    c0 = kn0; c1 = kn1;
    for (int i = 0; i < 10; i++) {
        uint32_t n0, n1, s0, s1;
        foldlike_split(c0, c1, n0, n1, s0, s1);
        uint32_t h0, h1, l0, l1;
        foldlike_split(s0, s1, h0, h1, l0, l1);   // randint internal split(sk)
        nkr.kh[i][0] = h0; nkr.kh[i][1] = h1;
        nkr.kl[i][0] = l0; nkr.kl[i][1] = l1;
        c0 = n0; c1 = n1;
    }

    // one-time host-side stream/event infra (host objects only; no device memory)
    static cudaStream_t s2 = nullptr;
    static cudaEvent_t eF = nullptr, eP = nullptr, eN = nullptr, eJ = nullptr;
    if (!s2) {
        cudaStreamCreateWithFlags(&s2, cudaStreamNonBlocking);
        cudaEventCreateWithFlags(&eF, cudaEventDisableTiming);
        cudaEventCreateWithFlags(&eP, cudaEventDisableTiming);
        cudaEventCreateWithFlags(&eN, cudaEventDisableTiming);
        cudaEventCreateWithFlags(&eJ, cudaEventDisableTiming);
    }

    // DAG: pos(s0) ∥ neg(s2); emit(s2) after both; loss(s0) after both; finalize(s0) after loss
    cudaEventRecord(eF, 0);
    cudaStreamWaitEvent(s2, eF, 0);

    pos_walk_kernel<<<NPOSW / 256, 256, 0, 0>>>(pk, batch,
        rowptr_ui, col_ui, rowcount_ui, nnz_ui, rowptr_iu, col_iu, rowcount_iu, nnz_iu);
    cudaEventRecord(eP, 0);

    neg_walk_kernel<<<NNEGW / 256, 256, 0, s2>>>(nkr, batch);
    cudaEventRecord(eN, s2);

    cudaStreamWaitEvent(s2, eP, 0);
    emit_kernel<<<(POS_ELEMS + NEG_ELEMS + 255) / 256, 256, 0, s2>>>(out);
    cudaEventRecord(eJ, s2);

    cudaStreamWaitEvent(0, eN, 0);
    loss_kernel<<<(NPOSW + NNEGW) / 8, 256, 0, 0>>>(emb);
    finalize_kernel<<<1, 32, 0, 0>>>(out);
    cudaStreamWaitEvent(0, eJ, 0);
}